// round 8
// baseline (speedup 1.0000x reference)
#include <cuda_runtime.h>

// LIF scan over T=8 timesteps, N = 4,194,304 independent spatial elements.
//   mem = mem*0.25*(1-spike) + x[t]; spike = (mem >= 0.5)
// Pure streaming: 128 MiB read + 128 MiB write, zero reuse -> DRAM-bound.
//
// R8: last matrix cell — streaming hints (.cs both ways) WITH interleaved
// per-t load/compute/store (no xv[8] front batch). Cuts regs 48 -> ~32,
// restoring ~84% occupancy while keeping evict-first policy. ncu kernel
// time proven invariant (~36.5 us, 73-75% DRAM = HBM roofline) across all
// seven prior variants; this probes only the timed replay-loop number.

#define DECAY  0.25f
#define THRESH 0.5f

static constexpr int T = 8;

__global__ __launch_bounds__(256) void lif_scan_kernel(
    const float4* __restrict__ x, float4* __restrict__ out, int n4)
{
    int i = blockIdx.x * blockDim.x + threadIdx.x;
    if (i >= n4) return;

    float4 mem   = make_float4(0.f, 0.f, 0.f, 0.f);
    float4 spike = make_float4(0.f, 0.f, 0.f, 0.f);

#pragma unroll
    for (int t = 0; t < T; t++) {
        const float4 xv = __ldcs(&x[(size_t)t * n4 + i]);
        mem.x = mem.x * (DECAY * (1.0f - spike.x)) + xv.x;
        mem.y = mem.y * (DECAY * (1.0f - spike.y)) + xv.y;
        mem.z = mem.z * (DECAY * (1.0f - spike.z)) + xv.z;
        mem.w = mem.w * (DECAY * (1.0f - spike.w)) + xv.w;
        spike.x = (mem.x >= THRESH) ? 1.0f : 0.0f;
        spike.y = (mem.y >= THRESH) ? 1.0f : 0.0f;
        spike.z = (mem.z >= THRESH) ? 1.0f : 0.0f;
        spike.w = (mem.w >= THRESH) ? 1.0f : 0.0f;
        __stcs(&out[(size_t)t * n4 + i], spike);
    }
}

extern "C" void kernel_launch(void* const* d_in, const int* in_sizes, int n_in,
                              void* d_out, int out_size)
{
    const float* x = (const float*)d_in[0];
    float* out = (float*)d_out;

    const int total = in_sizes[0];       // T * N
    const int n = total / T;             // elements per timestep (4,194,304)
    const int n4 = n / 4;                // float4 count per timestep (1,048,576)

    const int threads = 256;
    const int blocks = (n4 + threads - 1) / threads;

    lif_scan_kernel<<<blocks, threads>>>(
        (const float4*)x, (float4*)out, n4);
}

// round 9
// speedup vs baseline: 1.0402x; 1.0402x over previous
#include <cuda_runtime.h>

// LIF scan over T=8 timesteps, N = 4,194,304 independent spatial elements.
//   mem = mem*0.25*(1-spike) + x[t]; spike = (mem >= 0.5)
// Pure streaming: 128 MiB read + 128 MiB write, zero reuse -> DRAM-bound.
//
// FINAL — R3 shape. Complete lever sweep (R1-R8):
//   * front-batched MLP=8 is load-bearing: interleaving loads (R8) dropped
//     DRAM 74% -> 70.6% and ncu 36.4 -> 38.7 us. Keep the xv[8] batch.
//   * occupancy 32-84% non-binding; launch shape non-binding; .wt regressed;
//     .cs loads+stores is the timed-best policy (43.5 us, reproduced twice).
// Kernel is pinned at the balanced R/W HBM roofline (~5.85 TB/s for an
// irreducible 128 MiB read + 128 MiB write).

#define DECAY  0.25f
#define THRESH 0.5f

static constexpr int T = 8;

__global__ __launch_bounds__(256) void lif_scan_kernel(
    const float4* __restrict__ x, float4* __restrict__ out, int n4)
{
    int i = blockIdx.x * blockDim.x + threadIdx.x;
    if (i >= n4) return;

    // 8 independent streaming loads front-batched (MLP=8, evict-first).
    float4 xv[T];
#pragma unroll
    for (int t = 0; t < T; t++) {
        xv[t] = __ldcs(&x[(size_t)t * n4 + i]);
    }

    float4 mem   = make_float4(0.f, 0.f, 0.f, 0.f);
    float4 spike = make_float4(0.f, 0.f, 0.f, 0.f);

#pragma unroll
    for (int t = 0; t < T; t++) {
        mem.x = mem.x * (DECAY * (1.0f - spike.x)) + xv[t].x;
        mem.y = mem.y * (DECAY * (1.0f - spike.y)) + xv[t].y;
        mem.z = mem.z * (DECAY * (1.0f - spike.z)) + xv[t].z;
        mem.w = mem.w * (DECAY * (1.0f - spike.w)) + xv[t].w;
        spike.x = (mem.x >= THRESH) ? 1.0f : 0.0f;
        spike.y = (mem.y >= THRESH) ? 1.0f : 0.0f;
        spike.z = (mem.z >= THRESH) ? 1.0f : 0.0f;
        spike.w = (mem.w >= THRESH) ? 1.0f : 0.0f;
        __stcs(&out[(size_t)t * n4 + i], spike);
    }
}

extern "C" void kernel_launch(void* const* d_in, const int* in_sizes, int n_in,
                              void* d_out, int out_size)
{
    const float* x = (const float*)d_in[0];
    float* out = (float*)d_out;

    const int total = in_sizes[0];       // T * N
    const int n = total / T;             // elements per timestep (4,194,304)
    const int n4 = n / 4;                // float4 count per timestep (1,048,576)

    const int threads = 256;
    const int blocks = (n4 + threads - 1) / threads;

    lif_scan_kernel<<<blocks, threads>>>(
        (const float4*)x, (float4*)out, n4);
}